// round 16
// baseline (speedup 1.0000x reference)
#include <cuda_runtime.h>
#include <cuda_bf16.h>
#include <cuda_fp16.h>
#include <cstdint>

#define NN 100000
#define RR 3
#define EE 800000
#define F  128
#define NB 98          // scan chunks per relation: ceil(NN/1024)

// ---------------- scratch (device globals: allocation-free rule) ----------
__device__ __half g_tmp3[(size_t)RR * NN * F]; // per-relation GEMM outputs (fp16, ns-scaled)
__device__ __half g_act[(size_t)NN * F];       // layer-1 activations (fp16)
__device__ float  g_ns[RR * NN];               // rsqrt(max(deg_out,1))
__device__ float  g_nd[RR * NN];               // counts, then rsqrt(max(deg_in,1))
__device__ int    g_off[RR * NN];              // CSR offsets (per relation, by dst)
__device__ int    g_degi[RR * NN];             // int in-degree
__device__ int    g_cur[RR * NN];              // absolute bucket cursors
__device__ int    g_csrc[(size_t)RR * EE];     // dst-sorted src indices
__device__ int    g_bsum[RR * NB];             // per-chunk totals -> exclusive prefixes
__device__ int    g_scan_done;                 // tail-block election counter (self-resetting)
__device__ __half g_whf[2][RR][F * F];         // W fp16 planes [k][n]

// ---------------- prep: W fp16 planes + zero norms (merged) ---------------
__global__ void prep_zero_k(const float* __restrict__ W1, const float* __restrict__ W2) {
    int i = blockIdx.x * blockDim.x + threadIdx.x;
    if (i < 2 * RR * F * F) {
        int layer = i / (RR * F * F);
        int rem   = i % (RR * F * F);
        ((__half*)g_whf[layer])[rem] = __float2half_rn((layer ? W2 : W1)[rem]);
    }
    if (i < RR * NN) { g_ns[i] = 0.f; g_nd[i] = 0.f; }
}

// ---------------- degree count (2D grid: y = relation) --------------------
__global__ void degree_k(const int* __restrict__ src, const int* __restrict__ dst) {
    int e = blockIdx.x * blockDim.x + threadIdx.x;
    int r = blockIdx.y;
    if (e < EE) {
        atomicAdd(&g_ns[r * NN + src[r * EE + e]], 1.0f);
        atomicAdd(&g_nd[r * NN + dst[r * EE + e]], 1.0f);
    }
}

// ---------------- src-norm finalize (all the GEMM needs) ------------------
__global__ void ns_fin_k() {
    int i = blockIdx.x * blockDim.x + threadIdx.x;
    if (i < RR * NN) g_ns[i] = rsqrtf(fmaxf(g_ns[i], 1.0f));
}

// ---- scan phase 1 + fused tail-block phase 2 -----------------------------
__global__ void scan_part_k() {
    int r   = blockIdx.y;
    int idx = blockIdx.x * 1024 + threadIdx.x;
    int lane = threadIdx.x & 31, wid = threadIdx.x >> 5;

    int v = 0;
    if (idx < NN) v = (int)g_nd[r * NN + idx];

    int x = v;
#pragma unroll
    for (int o = 1; o < 32; o <<= 1) {
        int y = __shfl_up_sync(0xFFFFFFFFu, x, o);
        if (lane >= o) x += y;
    }
    __shared__ int wsum[32];
    __shared__ int sh_last;
    if (lane == 31) wsum[wid] = x;
    __syncthreads();
    if (wid == 0) {
        int w = wsum[lane];
#pragma unroll
        for (int o = 1; o < 32; o <<= 1) {
            int y = __shfl_up_sync(0xFFFFFFFFu, w, o);
            if (lane >= o) w += y;
        }
        wsum[lane] = w;
    }
    __syncthreads();

    int excl = x - v + (wid ? wsum[wid - 1] : 0);
    if (idx < NN) {
        g_off[r * NN + idx]  = excl;
        g_degi[r * NN + idx] = v;
    }
    if (threadIdx.x == 0) {
        g_bsum[r * NB + blockIdx.x] = wsum[31];
        __threadfence();
        int done = atomicAdd(&g_scan_done, 1);
        sh_last = (done == NB * RR - 1);
    }
    __syncthreads();

    if (sh_last) {
        __shared__ int sh[RR * 128];
        int t = threadIdx.x;
        int rr = t >> 7, j = t & 127;
        int bv = 0;
        if (t < RR * 128) {
            bv = (j < NB) ? g_bsum[rr * NB + j] : 0;
            sh[t] = bv;
        }
        __syncthreads();
#pragma unroll
        for (int o = 1; o < 128; o <<= 1) {
            int y = 0;
            if (t < RR * 128 && j >= o) y = sh[rr * 128 + j - o];
            __syncthreads();
            if (t < RR * 128) sh[t] += y;
            __syncthreads();
        }
        if (t < RR * 128 && j < NB) g_bsum[rr * NB + j] = sh[t] - bv;
        if (t == 0) g_scan_done = 0;
    }
}

// ---- dst-norm finalize + apply chunk prefix + cursors --------------------
__global__ void nd_fin_k() {
    int i = blockIdx.x * blockDim.x + threadIdx.x;
    if (i < RR * NN) {
        int r = i / NN, idx = i - r * NN;
        int off = g_off[i] + g_bsum[r * NB + (idx >> 10)];
        g_off[i] = off;
        g_cur[i] = off;
        g_nd[i] = rsqrtf(fmaxf(g_nd[i], 1.0f));
    }
}

__global__ void fill_csr_k(const int* __restrict__ src, const int* __restrict__ dst) {
    int e = blockIdx.x * blockDim.x + threadIdx.x;
    int r = blockIdx.y;
    if (e < EE) {
        int pos = atomicAdd(&g_cur[r * NN + dst[r * EE + e]], 1);
        g_csrc[(size_t)r * EE + pos] = src[r * EE + e];
    }
}

// ---------------- streamed-B fp16 tensor-core GEMM ------------------------
// g_tmp3[r] = (X @ W[r]) * ns_r[row]  (fp16 store)
// A (64x128 fp16) smem-resident (fp32 or fp16 source); B streamed as
// 64-k-row chunks, cp.async double-buffered.  52.2 KB smem -> 4 CTAs/SM.
#define BM   64
#define PA   136
#define APLANE (BM * PA)      // elems of A plane
#define B64    (64 * PA)      // elems per B chunk
#define NCHUNK (RR * 2)       // 6 chunks of 64 k-rows
#define GEMM_SMEM ((APLANE + 2 * B64) * 2)   // 52224 bytes

#define MMA_F16(d, a, b) \
    asm volatile("mma.sync.aligned.m16n8k16.row.col.f32.f16.f16.f32 " \
                 "{%0,%1,%2,%3}, {%4,%5,%6,%7}, {%8,%9}, {%0,%1,%2,%3};" \
                 : "+f"((d)[0]), "+f"((d)[1]), "+f"((d)[2]), "+f"((d)[3]) \
                 : "r"((a)[0]), "r"((a)[1]), "r"((a)[2]), "r"((a)[3]), \
                   "r"((b)[0]), "r"((b)[1]))

#define LDSM_X4(r, addr) \
    asm volatile("ldmatrix.sync.aligned.m8n8.x4.shared.b16 {%0,%1,%2,%3}, [%4];" \
                 : "=r"((r)[0]), "=r"((r)[1]), "=r"((r)[2]), "=r"((r)[3]) \
                 : "r"(addr))

#define LDSM_X4_T(r, addr) \
    asm volatile("ldmatrix.sync.aligned.m8n8.x4.trans.shared.b16 {%0,%1,%2,%3}, [%4];" \
                 : "=r"((r)[0]), "=r"((r)[1]), "=r"((r)[2]), "=r"((r)[3]) \
                 : "r"(addr))

__device__ __forceinline__ void cp_async16(uint32_t dst, const void* src) {
    asm volatile("cp.async.cg.shared.global [%0], [%1], 16;" :: "r"(dst), "l"(src));
}
#define CP_COMMIT() asm volatile("cp.async.commit_group;" ::: "memory")
#define CP_WAIT1()  asm volatile("cp.async.wait_group 1;" ::: "memory")
#define CP_WAIT0()  asm volatile("cp.async.wait_group 0;" ::: "memory")

__global__ void __launch_bounds__(256, 4)
gemm3_k(const float* __restrict__ Xf, const __half* __restrict__ Xh,
        int layer, __half* __restrict__ outp) {
    extern __shared__ __align__(16) __half sh[];
    __half* Ah = sh;                             // [64][PA]

    int t = threadIdx.x;
    int row0 = blockIdx.x * BM;

    uint32_t sbase = (uint32_t)__cvta_generic_to_shared(sh);
    uint32_t sbB   = sbase + APLANE * 2;         // byte addr of buf0 B

    // ---- prefetch chunk 0 of B while filling A (64x128 fp16 = 4 cp/thread)
    {
        const __half* hs = g_whf[layer][0];
#pragma unroll
        for (int i = 0; i < 4; i++) {
            int f = t + 256 * i;                 // 0..1023
            int k = f >> 4, n8 = (f & 15) << 3;
            cp_async16(sbB + (uint32_t)(k * PA + n8) * 2, hs + k * F + n8);
        }
        CP_COMMIT();
    }

    // ---- fill A: [m=64][k=128] fp16 (from fp32 x or fp16 act) ----
    if (Xh == nullptr) {
#pragma unroll
        for (int i = 0; i < 8; i++) {
            int f   = t + 256 * i;
            int row = f >> 5;
            int c4  = (f & 31) << 2;
            int grow = row0 + row;
            float4 v = make_float4(0.f, 0.f, 0.f, 0.f);
            if (grow < NN) v = *reinterpret_cast<const float4*>(Xf + (size_t)grow * F + c4);
            int base = row * PA + c4;
            *reinterpret_cast<__half2*>(&Ah[base])     = __floats2half2_rn(v.x, v.y);
            *reinterpret_cast<__half2*>(&Ah[base + 2]) = __floats2half2_rn(v.z, v.w);
        }
    } else {
#pragma unroll
        for (int i = 0; i < 8; i++) {
            int f   = t + 256 * i;
            int row = f >> 5;
            int c4  = (f & 31) << 2;
            int grow = row0 + row;
            uint2 v = make_uint2(0u, 0u);
            if (grow < NN) v = *reinterpret_cast<const uint2*>(Xh + (size_t)grow * F + c4);
            *reinterpret_cast<uint2*>(&Ah[row * PA + c4]) = v;
        }
    }

    int lane = t & 31, warp = t >> 5;
    int mbase = (warp & 1) * 32;    // 2 m-groups of 32 rows
    int nbase = (warp >> 1) * 32;   // 4 n-groups of 32 cols

    int lrow = lane & 7;
    int m8   = ((lane >> 3) & 1) << 3;
    int k8   = ((lane >> 4) & 1) << 3;

    unsigned aA0 = sbase + (unsigned)(((mbase + lrow + m8) * PA + k8) * 2);
    unsigned aA1 = aA0 + 16 * PA * 2;
    unsigned bwoff = (unsigned)(((lrow + m8) * PA + nbase + k8) * 2);

    int grp = lane >> 2;
    int cof = (lane & 3) * 2;

    for (int r = 0; r < RR; r++) {
        float acc[2][4][4];
#pragma unroll
        for (int mt = 0; mt < 2; mt++)
#pragma unroll
            for (int nt = 0; nt < 4; nt++)
#pragma unroll
                for (int c = 0; c < 4; c++) acc[mt][nt][c] = 0.f;

#pragma unroll
        for (int ch = 0; ch < 2; ch++) {
            int c = r * 2 + ch;
            __syncthreads();   // prior reads of buf[(c+1)&1] done (A fill on c=0)
            if (c + 1 < NCHUNK) {
                int cn = c + 1;
                const __half* hs = g_whf[layer][cn >> 1] + (cn & 1) * 64 * F;
                uint32_t bb = sbB + (uint32_t)(cn & 1) * (B64 * 2);
#pragma unroll
                for (int i = 0; i < 4; i++) {
                    int f = t + 256 * i;
                    int k = f >> 4, n8 = (f & 15) << 3;
                    cp_async16(bb + (uint32_t)(k * PA + n8) * 2, hs + k * F + n8);
                }
                CP_COMMIT();
                CP_WAIT1();
            } else {
                CP_WAIT0();
            }
            __syncthreads();   // chunk c visible to all warps

            uint32_t bufb = sbB + (uint32_t)(c & 1) * (B64 * 2) + bwoff;
#pragma unroll
            for (int kci = 0; kci < 4; kci++) {
                int gk = ch * 4 + kci;
                unsigned aOff = gk * 32;
                unsigned bB = bufb + kci * 16 * PA * 2;

                unsigned ah[2][4];
                LDSM_X4(ah[0], aA0 + aOff);
                LDSM_X4(ah[1], aA1 + aOff);

#pragma unroll
                for (int np = 0; np < 2; np++) {
                    unsigned bh[4];
                    LDSM_X4_T(bh, bB + np * 16 * 2);
                    unsigned* bh0 = bh;
                    unsigned* bh1 = bh + 2;
#pragma unroll
                    for (int mt = 0; mt < 2; mt++) {
                        MMA_F16(acc[mt][2 * np],     ah[mt], bh0);
                        MMA_F16(acc[mt][2 * np + 1], ah[mt], bh1);
                    }
                }
            }
        }

        // ---- epilogue: scale by norm_src[row], store fp16 ----
        const float* nsr = g_ns + r * NN;
        __half* op = outp + (size_t)r * NN * F;
#pragma unroll
        for (int mt = 0; mt < 2; mt++) {
            int rA = row0 + mbase + mt * 16 + grp;
            int rB = rA + 8;
            float sA = (rA < NN) ? nsr[rA] : 0.f;
            float sB = (rB < NN) ? nsr[rB] : 0.f;
#pragma unroll
            for (int nt = 0; nt < 4; nt++) {
                int col = nbase + nt * 8 + cof;
                if (rA < NN)
                    *reinterpret_cast<__half2*>(op + (size_t)rA * F + col) =
                        __floats2half2_rn(acc[mt][nt][0] * sA, acc[mt][nt][1] * sA);
                if (rB < NN)
                    *reinterpret_cast<__half2*>(op + (size_t)rB * F + col) =
                        __floats2half2_rn(acc[mt][nt][2] * sB, acc[mt][nt][3] * sB);
            }
        }
    }
}

// ---------------- fused aggregation: one warp per node, all 3 relations ---
// Round-14 shape (uint2 lanes, 8-edge unroll) + cross-relation first-batch
// index prefetch: ib[3][8] loaded before any gathers so index-load latency
// overlaps across relations.  Accumulation order identical to round 14.
__global__ void __launch_bounds__(256)
agg_all_k(const __half* __restrict__ tmp3, const float* __restrict__ bias,
          __half* __restrict__ out_h, float* __restrict__ out_f, int relu) {
    int warp = (blockIdx.x * blockDim.x + threadIdx.x) >> 5;
    int lane = threadIdx.x & 31;
    if (warp >= NN) return;
    int node = warp;
    int c4 = lane * 4;

    int off0 = g_off[node],  off1 = g_off[NN + node],  off2 = g_off[2 * NN + node];
    int cnt0 = g_degi[node], cnt1 = g_degi[NN + node], cnt2 = g_degi[2 * NN + node];
    float nd0 = g_nd[node],  nd1 = g_nd[NN + node],    nd2 = g_nd[2 * NN + node];
    int offs[RR]  = {off0, off1, off2};
    int cnts[RR]  = {cnt0, cnt1, cnt2};
    float nds[RR] = {nd0, nd1, nd2};

    // ---- prefetch first-batch indices for ALL relations ----
    int ib[RR][8];
#pragma unroll
    for (int r = 0; r < RR; r++) {
        const int* lst = g_csrc + (size_t)r * EE + offs[r];
#pragma unroll
        for (int q = 0; q < 8; q++)
            ib[r][q] = (q < cnts[r]) ? __ldg(lst + q) : 0;
    }

    float4 acc;
    {
        float4 b0 = *reinterpret_cast<const float4*>(bias + c4);
        float4 b1 = *reinterpret_cast<const float4*>(bias + F + c4);
        float4 b2 = *reinterpret_cast<const float4*>(bias + 2 * F + c4);
        acc = make_float4(b0.x + b1.x + b2.x, b0.y + b1.y + b2.y,
                          b0.z + b1.z + b2.z, b0.w + b1.w + b2.w);
    }

#pragma unroll
    for (int r = 0; r < RR; r++) {
        int cnt = cnts[r];
        const int* lst = g_csrc + (size_t)r * EE + offs[r];
        const __half* tmp = tmp3 + (size_t)r * NN * F;

        float4 part = make_float4(0.f, 0.f, 0.f, 0.f);

        // ---- first batch: prefetched indices, up to 8 edges ----
        int take = cnt < 8 ? cnt : 8;
        {
            uint2 w[8];
#pragma unroll
            for (int q = 0; q < 8; q++)
                if (q < take)
                    w[q] = *reinterpret_cast<const uint2*>(tmp + (size_t)ib[r][q] * F + c4);
#pragma unroll
            for (int q = 0; q < 8; q++)
                if (q < take) {
                    float2 a = __half22float2(*reinterpret_cast<__half2*>(&w[q].x));
                    float2 b = __half22float2(*reinterpret_cast<__half2*>(&w[q].y));
                    part.x += a.x; part.y += a.y; part.z += b.x; part.w += b.y;
                }
        }

        // ---- remainder: round-14 loops starting at j=8 ----
        int j = 8;
        for (; j + 8 <= cnt; j += 8) {
            int s[8];
#pragma unroll
            for (int q = 0; q < 8; q++) s[q] = __ldg(lst + j + q);
            uint2 w[8];
#pragma unroll
            for (int q = 0; q < 8; q++)
                w[q] = *reinterpret_cast<const uint2*>(tmp + (size_t)s[q] * F + c4);
#pragma unroll
            for (int q = 0; q < 8; q++) {
                float2 a = __half22float2(*reinterpret_cast<__half2*>(&w[q].x));
                float2 b = __half22float2(*reinterpret_cast<__half2*>(&w[q].y));
                part.x += a.x; part.y += a.y; part.z += b.x; part.w += b.y;
            }
        }
        for (; j + 2 <= cnt; j += 2) {
            int s0 = __ldg(lst + j);
            int s1 = __ldg(lst + j + 1);
            uint2 w0 = *reinterpret_cast<const uint2*>(tmp + (size_t)s0 * F + c4);
            uint2 w1 = *reinterpret_cast<const uint2*>(tmp + (size_t)s1 * F + c4);
            float2 a0 = __half22float2(*reinterpret_cast<__half2*>(&w0.x));
            float2 b0 = __half22float2(*reinterpret_cast<__half2*>(&w0.y));
            float2 a1 = __half22float2(*reinterpret_cast<__half2*>(&w1.x));
            float2 b1 = __half22float2(*reinterpret_cast<__half2*>(&w1.y));
            part.x += a0.x + a1.x; part.y += a0.y + a1.y;
            part.z += b0.x + b1.x; part.w += b0.y + b1.y;
        }
        if (j < cnt) {
            int s = __ldg(lst + j);
            uint2 w = *reinterpret_cast<const uint2*>(tmp + (size_t)s * F + c4);
            float2 a = __half22float2(*reinterpret_cast<__half2*>(&w.x));
            float2 b = __half22float2(*reinterpret_cast<__half2*>(&w.y));
            part.x += a.x; part.y += a.y; part.z += b.x; part.w += b.y;
        }

        float nd = nds[r];
        acc.x += part.x * nd; acc.y += part.y * nd;
        acc.z += part.z * nd; acc.w += part.w * nd;
    }

    if (relu) {
        acc.x = fmaxf(acc.x, 0.f); acc.y = fmaxf(acc.y, 0.f);
        acc.z = fmaxf(acc.z, 0.f); acc.w = fmaxf(acc.w, 0.f);
    }
    if (out_h) {
        __half2 h0 = __floats2half2_rn(acc.x, acc.y);
        __half2 h1 = __floats2half2_rn(acc.z, acc.w);
        *reinterpret_cast<uint2*>(out_h + (size_t)node * F + c4) =
            make_uint2(*reinterpret_cast<uint32_t*>(&h0), *reinterpret_cast<uint32_t*>(&h1));
    } else {
        *reinterpret_cast<float4*>(out_f + (size_t)node * F + c4) = acc;
    }
}

// ---------------- launch ---------------------------------------------------
extern "C" void kernel_launch(void* const* d_in, const int* in_sizes, int n_in,
                              void* d_out, int out_size) {
    const float* x   = (const float*)d_in[0];
    const int*   src = (const int*)  d_in[1];
    const int*   dst = (const int*)  d_in[2];
    const float* W1  = (const float*)d_in[3];
    const float* b1  = (const float*)d_in[4];
    const float* W2  = (const float*)d_in[5];
    const float* b2  = (const float*)d_in[6];
    float* out = (float*)d_out;

    void* p;
    cudaGetSymbolAddress(&p, g_act);  __half* act = (__half*)p;
    cudaGetSymbolAddress(&p, g_tmp3); __half* tmp = (__half*)p;

    cudaFuncSetAttribute(gemm3_k,
                         cudaFuncAttributeMaxDynamicSharedMemorySize, GEMM_SMEM);

    const int T = 256;
    int gemm_blocks = (NN + BM - 1) / BM;      // 1563
    int agg_blocks  = (NN * 32 + T - 1) / T;   // warp per node
    int edge_blocks = (EE + T - 1) / T;

    // 0: W fp16 prep + zero norms
    prep_zero_k<<<(RR * NN + T - 1) / T, T>>>(W1, W2);
    // 1: degrees
    degree_k<<<dim3(edge_blocks, RR), T>>>(src, dst);
    // 2: src norms (all the GEMM needs)
    ns_fin_k<<<(RR * NN + T - 1) / T, T>>>();
    // 3: layer-1 GEMM  (profiled slot)
    gemm3_k<<<gemm_blocks, T, GEMM_SMEM>>>(x, nullptr, 0, tmp);
    // 4: scan (+fused chunk-total scan in tail block)
    scan_part_k<<<dim3(NB, RR), 1024>>>();
    // 5: dst norms + offsets + cursors
    nd_fin_k<<<(RR * NN + T - 1) / T, T>>>();
    // 6: CSR fill
    fill_csr_k<<<dim3(edge_blocks, RR), T>>>(src, dst);
    // 7: layer-1 aggregation (+bias+ReLU) -> fp16 activations
    agg_all_k<<<agg_blocks, T>>>(tmp, b1, act, nullptr, 1);
    // 8: layer-2 GEMM (fp16 activations in)
    gemm3_k<<<gemm_blocks, T, GEMM_SMEM>>>(nullptr, act, 1, tmp);
    // 9: layer-2 aggregation (+bias) -> fp32 output
    agg_all_k<<<agg_blocks, T>>>(tmp, b2, nullptr, out, 0);
}

// round 17
// speedup vs baseline: 1.9611x; 1.9611x over previous
#include <cuda_runtime.h>
#include <cuda_bf16.h>
#include <cuda_fp16.h>
#include <cstdint>

#define NN 100000
#define RR 3
#define EE 800000
#define F  128
#define NB 98          // scan chunks per relation: ceil(NN/1024)

// ---------------- scratch (device globals: allocation-free rule) ----------
__device__ __half g_tmp3[(size_t)RR * NN * F]; // per-relation GEMM outputs (fp16, ns-scaled)
__device__ __half g_act[(size_t)NN * F];       // layer-1 activations (fp16)
__device__ float  g_ns[RR * NN];               // rsqrt(max(deg_out,1))
__device__ float  g_nd[RR * NN];               // counts, then rsqrt(max(deg_in,1))
__device__ int    g_off[RR * NN];              // CSR offsets (per relation, by dst)
__device__ int    g_degi[RR * NN];             // int in-degree
__device__ int    g_cur[RR * NN];              // absolute bucket cursors
__device__ int    g_csrc[(size_t)RR * EE];     // dst-sorted src indices
__device__ int    g_bsum[RR * NB];             // per-chunk totals -> exclusive prefixes
__device__ int    g_scan_done;                 // tail-block election counter (self-resetting)
__device__ __half g_whf[2][RR][F * F];         // W fp16 planes [k][n]

// ---------------- prep: W fp16 planes + zero norms (merged) ---------------
__global__ void prep_zero_k(const float* __restrict__ W1, const float* __restrict__ W2) {
    int i = blockIdx.x * blockDim.x + threadIdx.x;
    if (i < 2 * RR * F * F) {
        int layer = i / (RR * F * F);
        int rem   = i % (RR * F * F);
        ((__half*)g_whf[layer])[rem] = __float2half_rn((layer ? W2 : W1)[rem]);
    }
    if (i < RR * NN) { g_ns[i] = 0.f; g_nd[i] = 0.f; }
}

// ---------------- degree count (2D grid: y = relation) --------------------
__global__ void degree_k(const int* __restrict__ src, const int* __restrict__ dst) {
    int e = blockIdx.x * blockDim.x + threadIdx.x;
    int r = blockIdx.y;
    if (e < EE) {
        atomicAdd(&g_ns[r * NN + src[r * EE + e]], 1.0f);
        atomicAdd(&g_nd[r * NN + dst[r * EE + e]], 1.0f);
    }
}

// ---- scan phase 1 (+ src-norm finalize) + fused tail-block phase 2 -------
__global__ void scan_part_k() {
    int r   = blockIdx.y;
    int idx = blockIdx.x * 1024 + threadIdx.x;
    int lane = threadIdx.x & 31, wid = threadIdx.x >> 5;

    int v = 0;
    if (idx < NN) {
        int gi = r * NN + idx;
        v = (int)g_nd[gi];
        g_ns[gi] = rsqrtf(fmaxf(g_ns[gi], 1.0f));   // fused ns finalize
    }

    int x = v;
#pragma unroll
    for (int o = 1; o < 32; o <<= 1) {
        int y = __shfl_up_sync(0xFFFFFFFFu, x, o);
        if (lane >= o) x += y;
    }
    __shared__ int wsum[32];
    __shared__ int sh_last;
    if (lane == 31) wsum[wid] = x;
    __syncthreads();
    if (wid == 0) {
        int w = wsum[lane];
#pragma unroll
        for (int o = 1; o < 32; o <<= 1) {
            int y = __shfl_up_sync(0xFFFFFFFFu, w, o);
            if (lane >= o) w += y;
        }
        wsum[lane] = w;
    }
    __syncthreads();

    int excl = x - v + (wid ? wsum[wid - 1] : 0);
    if (idx < NN) {
        g_off[r * NN + idx]  = excl;
        g_degi[r * NN + idx] = v;
    }
    if (threadIdx.x == 0) {
        g_bsum[r * NB + blockIdx.x] = wsum[31];
        __threadfence();
        int done = atomicAdd(&g_scan_done, 1);
        sh_last = (done == NB * RR - 1);
    }
    __syncthreads();

    if (sh_last) {
        __shared__ int sh[RR * 128];
        int t = threadIdx.x;
        int rr = t >> 7, j = t & 127;
        int bv = 0;
        if (t < RR * 128) {
            bv = (j < NB) ? g_bsum[rr * NB + j] : 0;
            sh[t] = bv;
        }
        __syncthreads();
#pragma unroll
        for (int o = 1; o < 128; o <<= 1) {
            int y = 0;
            if (t < RR * 128 && j >= o) y = sh[rr * 128 + j - o];
            __syncthreads();
            if (t < RR * 128) sh[t] += y;
            __syncthreads();
        }
        if (t < RR * 128 && j < NB) g_bsum[rr * NB + j] = sh[t] - bv;
        if (t == 0) g_scan_done = 0;
    }
}

// ---- dst-norm finalize + apply chunk prefix + cursors --------------------
__global__ void nd_fin_k() {
    int i = blockIdx.x * blockDim.x + threadIdx.x;
    if (i < RR * NN) {
        int r = i / NN, idx = i - r * NN;
        int off = g_off[i] + g_bsum[r * NB + (idx >> 10)];
        g_off[i] = off;
        g_cur[i] = off;
        g_nd[i] = rsqrtf(fmaxf(g_nd[i], 1.0f));
    }
}

__global__ void fill_csr_k(const int* __restrict__ src, const int* __restrict__ dst) {
    int e = blockIdx.x * blockDim.x + threadIdx.x;
    int r = blockIdx.y;
    if (e < EE) {
        int pos = atomicAdd(&g_cur[r * NN + dst[r * EE + e]], 1);
        g_csrc[(size_t)r * EE + pos] = src[r * EE + e];
    }
}

// ---------------- streamed-B fp16 tensor-core GEMM ------------------------
// g_tmp3[r] = (X @ W[r]) * ns_r[row]  (fp16 store)
// A (64x128 fp16) smem-resident (fp32 or fp16 source); B streamed as
// 64-k-row chunks, cp.async double-buffered.  52.2 KB smem -> 4 CTAs/SM.
#define BM   64
#define PA   136
#define APLANE (BM * PA)      // elems of A plane
#define B64    (64 * PA)      // elems per B chunk
#define NCHUNK (RR * 2)       // 6 chunks of 64 k-rows
#define GEMM_SMEM ((APLANE + 2 * B64) * 2)   // 52224 bytes

#define MMA_F16(d, a, b) \
    asm volatile("mma.sync.aligned.m16n8k16.row.col.f32.f16.f16.f32 " \
                 "{%0,%1,%2,%3}, {%4,%5,%6,%7}, {%8,%9}, {%0,%1,%2,%3};" \
                 : "+f"((d)[0]), "+f"((d)[1]), "+f"((d)[2]), "+f"((d)[3]) \
                 : "r"((a)[0]), "r"((a)[1]), "r"((a)[2]), "r"((a)[3]), \
                   "r"((b)[0]), "r"((b)[1]))

#define LDSM_X4(r, addr) \
    asm volatile("ldmatrix.sync.aligned.m8n8.x4.shared.b16 {%0,%1,%2,%3}, [%4];" \
                 : "=r"((r)[0]), "=r"((r)[1]), "=r"((r)[2]), "=r"((r)[3]) \
                 : "r"(addr))

#define LDSM_X4_T(r, addr) \
    asm volatile("ldmatrix.sync.aligned.m8n8.x4.trans.shared.b16 {%0,%1,%2,%3}, [%4];" \
                 : "=r"((r)[0]), "=r"((r)1), "=r"((r)[2]), "=r"((r)[3]) \
                 : "r"(addr))
#undef LDSM_X4_T
#define LDSM_X4_T(r, addr) \
    asm volatile("ldmatrix.sync.aligned.m8n8.x4.trans.shared.b16 {%0,%1,%2,%3}, [%4];" \
                 : "=r"((r)[0]), "=r"((r)[1]), "=r"((r)[2]), "=r"((r)[3]) \
                 : "r"(addr))

__device__ __forceinline__ void cp_async16(uint32_t dst, const void* src) {
    asm volatile("cp.async.cg.shared.global [%0], [%1], 16;" :: "r"(dst), "l"(src));
}
#define CP_COMMIT() asm volatile("cp.async.commit_group;" ::: "memory")
#define CP_WAIT1()  asm volatile("cp.async.wait_group 1;" ::: "memory")
#define CP_WAIT0()  asm volatile("cp.async.wait_group 0;" ::: "memory")

__global__ void __launch_bounds__(256, 4)
gemm3_k(const float* __restrict__ Xf, const __half* __restrict__ Xh,
        int layer, __half* __restrict__ outp) {
    extern __shared__ __align__(16) __half sh[];
    __half* Ah = sh;                             // [64][PA]

    int t = threadIdx.x;
    int row0 = blockIdx.x * BM;

    uint32_t sbase = (uint32_t)__cvta_generic_to_shared(sh);
    uint32_t sbB   = sbase + APLANE * 2;         // byte addr of buf0 B

    // ---- prefetch chunk 0 of B while filling A (64x128 fp16 = 4 cp/thread)
    {
        const __half* hs = g_whf[layer][0];
#pragma unroll
        for (int i = 0; i < 4; i++) {
            int f = t + 256 * i;                 // 0..1023
            int k = f >> 4, n8 = (f & 15) << 3;
            cp_async16(sbB + (uint32_t)(k * PA + n8) * 2, hs + k * F + n8);
        }
        CP_COMMIT();
    }

    // ---- fill A: [m=64][k=128] fp16 (from fp32 x or fp16 act) ----
    if (Xh == nullptr) {
#pragma unroll
        for (int i = 0; i < 8; i++) {
            int f   = t + 256 * i;
            int row = f >> 5;
            int c4  = (f & 31) << 2;
            int grow = row0 + row;
            float4 v = make_float4(0.f, 0.f, 0.f, 0.f);
            if (grow < NN) v = *reinterpret_cast<const float4*>(Xf + (size_t)grow * F + c4);
            int base = row * PA + c4;
            *reinterpret_cast<__half2*>(&Ah[base])     = __floats2half2_rn(v.x, v.y);
            *reinterpret_cast<__half2*>(&Ah[base + 2]) = __floats2half2_rn(v.z, v.w);
        }
    } else {
#pragma unroll
        for (int i = 0; i < 8; i++) {
            int f   = t + 256 * i;
            int row = f >> 5;
            int c4  = (f & 31) << 2;
            int grow = row0 + row;
            uint2 v = make_uint2(0u, 0u);
            if (grow < NN) v = *reinterpret_cast<const uint2*>(Xh + (size_t)grow * F + c4);
            *reinterpret_cast<uint2*>(&Ah[row * PA + c4]) = v;
        }
    }

    int lane = t & 31, warp = t >> 5;
    int mbase = (warp & 1) * 32;    // 2 m-groups of 32 rows
    int nbase = (warp >> 1) * 32;   // 4 n-groups of 32 cols

    int lrow = lane & 7;
    int m8   = ((lane >> 3) & 1) << 3;
    int k8   = ((lane >> 4) & 1) << 3;

    unsigned aA0 = sbase + (unsigned)(((mbase + lrow + m8) * PA + k8) * 2);
    unsigned aA1 = aA0 + 16 * PA * 2;
    unsigned bwoff = (unsigned)(((lrow + m8) * PA + nbase + k8) * 2);

    int grp = lane >> 2;
    int cof = (lane & 3) * 2;

    for (int r = 0; r < RR; r++) {
        float acc[2][4][4];
#pragma unroll
        for (int mt = 0; mt < 2; mt++)
#pragma unroll
            for (int nt = 0; nt < 4; nt++)
#pragma unroll
                for (int c = 0; c < 4; c++) acc[mt][nt][c] = 0.f;

#pragma unroll
        for (int ch = 0; ch < 2; ch++) {
            int c = r * 2 + ch;
            __syncthreads();   // prior reads of buf[(c+1)&1] done (A fill on c=0)
            if (c + 1 < NCHUNK) {
                int cn = c + 1;
                const __half* hs = g_whf[layer][cn >> 1] + (cn & 1) * 64 * F;
                uint32_t bb = sbB + (uint32_t)(cn & 1) * (B64 * 2);
#pragma unroll
                for (int i = 0; i < 4; i++) {
                    int f = t + 256 * i;
                    int k = f >> 4, n8 = (f & 15) << 3;
                    cp_async16(bb + (uint32_t)(k * PA + n8) * 2, hs + k * F + n8);
                }
                CP_COMMIT();
                CP_WAIT1();
            } else {
                CP_WAIT0();
            }
            __syncthreads();   // chunk c visible to all warps

            uint32_t bufb = sbB + (uint32_t)(c & 1) * (B64 * 2) + bwoff;
#pragma unroll
            for (int kci = 0; kci < 4; kci++) {
                int gk = ch * 4 + kci;
                unsigned aOff = gk * 32;
                unsigned bB = bufb + kci * 16 * PA * 2;

                unsigned ah[2][4];
                LDSM_X4(ah[0], aA0 + aOff);
                LDSM_X4(ah[1], aA1 + aOff);

#pragma unroll
                for (int np = 0; np < 2; np++) {
                    unsigned bh[4];
                    LDSM_X4_T(bh, bB + np * 16 * 2);
                    unsigned* bh0 = bh;
                    unsigned* bh1 = bh + 2;
#pragma unroll
                    for (int mt = 0; mt < 2; mt++) {
                        MMA_F16(acc[mt][2 * np],     ah[mt], bh0);
                        MMA_F16(acc[mt][2 * np + 1], ah[mt], bh1);
                    }
                }
            }
        }

        // ---- epilogue: scale by norm_src[row], store fp16 ----
        const float* nsr = g_ns + r * NN;
        __half* op = outp + (size_t)r * NN * F;
#pragma unroll
        for (int mt = 0; mt < 2; mt++) {
            int rA = row0 + mbase + mt * 16 + grp;
            int rB = rA + 8;
            float sA = (rA < NN) ? nsr[rA] : 0.f;
            float sB = (rB < NN) ? nsr[rB] : 0.f;
#pragma unroll
            for (int nt = 0; nt < 4; nt++) {
                int col = nbase + nt * 8 + cof;
                if (rA < NN)
                    *reinterpret_cast<__half2*>(op + (size_t)rA * F + col) =
                        __floats2half2_rn(acc[mt][nt][0] * sA, acc[mt][nt][1] * sA);
                if (rB < NN)
                    *reinterpret_cast<__half2*>(op + (size_t)rB * F + col) =
                        __floats2half2_rn(acc[mt][nt][2] * sB, acc[mt][nt][3] * sB);
            }
        }
    }
}

// ---------------- fused aggregation: one warp per node, all 3 relations ---
// Round-14 version verbatim (measured best).
__global__ void __launch_bounds__(256)
agg_all_k(const __half* __restrict__ tmp3, const float* __restrict__ bias,
          __half* __restrict__ out_h, float* __restrict__ out_f, int relu) {
    int warp = (blockIdx.x * blockDim.x + threadIdx.x) >> 5;
    int lane = threadIdx.x & 31;
    if (warp >= NN) return;
    int node = warp;
    int c4 = lane * 4;

    int off0 = g_off[node],  off1 = g_off[NN + node],  off2 = g_off[2 * NN + node];
    int cnt0 = g_degi[node], cnt1 = g_degi[NN + node], cnt2 = g_degi[2 * NN + node];
    float nd0 = g_nd[node],  nd1 = g_nd[NN + node],    nd2 = g_nd[2 * NN + node];
    int offs[RR]  = {off0, off1, off2};
    int cnts[RR]  = {cnt0, cnt1, cnt2};
    float nds[RR] = {nd0, nd1, nd2};

    float4 acc;
    {
        float4 b0 = *reinterpret_cast<const float4*>(bias + c4);
        float4 b1 = *reinterpret_cast<const float4*>(bias + F + c4);
        float4 b2 = *reinterpret_cast<const float4*>(bias + 2 * F + c4);
        acc = make_float4(b0.x + b1.x + b2.x, b0.y + b1.y + b2.y,
                          b0.z + b1.z + b2.z, b0.w + b1.w + b2.w);
    }

#pragma unroll
    for (int r = 0; r < RR; r++) {
        int cnt = cnts[r];
        const int* lst = g_csrc + (size_t)r * EE + offs[r];
        const __half* tmp = tmp3 + (size_t)r * NN * F;

        float4 part = make_float4(0.f, 0.f, 0.f, 0.f);
        int j = 0;
        for (; j + 8 <= cnt; j += 8) {
            int s[8];
#pragma unroll
            for (int q = 0; q < 8; q++) s[q] = __ldg(lst + j + q);
            uint2 w[8];
#pragma unroll
            for (int q = 0; q < 8; q++)
                w[q] = *reinterpret_cast<const uint2*>(tmp + (size_t)s[q] * F + c4);
#pragma unroll
            for (int q = 0; q < 8; q++) {
                float2 a = __half22float2(*reinterpret_cast<__half2*>(&w[q].x));
                float2 b = __half22float2(*reinterpret_cast<__half2*>(&w[q].y));
                part.x += a.x; part.y += a.y; part.z += b.x; part.w += b.y;
            }
        }
        for (; j + 2 <= cnt; j += 2) {
            int s0 = __ldg(lst + j);
            int s1 = __ldg(lst + j + 1);
            uint2 w0 = *reinterpret_cast<const uint2*>(tmp + (size_t)s0 * F + c4);
            uint2 w1 = *reinterpret_cast<const uint2*>(tmp + (size_t)s1 * F + c4);
            float2 a0 = __half22float2(*reinterpret_cast<__half2*>(&w0.x));
            float2 b0 = __half22float2(*reinterpret_cast<__half2*>(&w0.y));
            float2 a1 = __half22float2(*reinterpret_cast<__half2*>(&w1.x));
            float2 b1 = __half22float2(*reinterpret_cast<__half2*>(&w1.y));
            part.x += a0.x + a1.x; part.y += a0.y + a1.y;
            part.z += b0.x + b1.x; part.w += b0.y + b1.y;
        }
        if (j < cnt) {
            int s = __ldg(lst + j);
            uint2 w = *reinterpret_cast<const uint2*>(tmp + (size_t)s * F + c4);
            float2 a = __half22float2(*reinterpret_cast<__half2*>(&w.x));
            float2 b = __half22float2(*reinterpret_cast<__half2*>(&w.y));
            part.x += a.x; part.y += a.y; part.z += b.x; part.w += b.y;
        }

        float nd = nds[r];
        acc.x += part.x * nd; acc.y += part.y * nd;
        acc.z += part.z * nd; acc.w += part.w * nd;
    }

    if (relu) {
        acc.x = fmaxf(acc.x, 0.f); acc.y = fmaxf(acc.y, 0.f);
        acc.z = fmaxf(acc.z, 0.f); acc.w = fmaxf(acc.w, 0.f);
    }
    if (out_h) {
        __half2 h0 = __floats2half2_rn(acc.x, acc.y);
        __half2 h1 = __floats2half2_rn(acc.z, acc.w);
        *reinterpret_cast<uint2*>(out_h + (size_t)node * F + c4) =
            make_uint2(*reinterpret_cast<uint32_t*>(&h0), *reinterpret_cast<uint32_t*>(&h1));
    } else {
        *reinterpret_cast<float4*>(out_f + (size_t)node * F + c4) = acc;
    }
}

// ---------------- launch ---------------------------------------------------
extern "C" void kernel_launch(void* const* d_in, const int* in_sizes, int n_in,
                              void* d_out, int out_size) {
    const float* x   = (const float*)d_in[0];
    const int*   src = (const int*)  d_in[1];
    const int*   dst = (const int*)  d_in[2];
    const float* W1  = (const float*)d_in[3];
    const float* b1  = (const float*)d_in[4];
    const float* W2  = (const float*)d_in[5];
    const float* b2  = (const float*)d_in[6];
    float* out = (float*)d_out;

    void* p;
    cudaGetSymbolAddress(&p, g_act);  __half* act = (__half*)p;
    cudaGetSymbolAddress(&p, g_tmp3); __half* tmp = (__half*)p;

    cudaFuncSetAttribute(gemm3_k,
                         cudaFuncAttributeMaxDynamicSharedMemorySize, GEMM_SMEM);

    const int T = 256;
    int gemm_blocks = (NN + BM - 1) / BM;      // 1563
    int agg_blocks  = (NN * 32 + T - 1) / T;   // warp per node
    int edge_blocks = (EE + T - 1) / T;

    // 0: W fp16 prep + zero norms
    prep_zero_k<<<(RR * NN + T - 1) / T, T>>>(W1, W2);
    // 1: degrees
    degree_k<<<dim3(edge_blocks, RR), T>>>(src, dst);
    // 2: scan (+ns finalize, +fused chunk-total scan in tail block)
    scan_part_k<<<dim3(NB, RR), 1024>>>();
    // 3: dst norms + offsets + cursors
    nd_fin_k<<<(RR * NN + T - 1) / T, T>>>();
    // 4: CSR fill
    fill_csr_k<<<dim3(edge_blocks, RR), T>>>(src, dst);
    // 5: layer-1 GEMM
    gemm3_k<<<gemm_blocks, T, GEMM_SMEM>>>(x, nullptr, 0, tmp);
    // 6: layer-1 aggregation (+bias+ReLU) -> fp16 activations
    agg_all_k<<<agg_blocks, T>>>(tmp, b1, act, nullptr, 1);
    // 7: layer-2 GEMM (fp16 activations in)
    gemm3_k<<<gemm_blocks, T, GEMM_SMEM>>>(nullptr, act, 1, tmp);
    // 8: layer-2 aggregation (+bias) -> fp32 output
    agg_all_k<<<agg_blocks, T>>>(tmp, b2, nullptr, out, 0);
}